// round 3
// baseline (speedup 1.0000x reference)
#include <cuda_runtime.h>
#include <cuda_bf16.h>
#include <cstdint>

#define D_FEAT 64
#define H_FEAT 128
#define N_MAX 100000
#define E_MAX 1600000

typedef unsigned long long u64;

// Scratch (static device arrays only — no allocation allowed)
__device__ float g_flow[(size_t)N_MAX * D_FEAT];   // 25.6 MB
__device__ int   g_deg[N_MAX];
__device__ int   g_cursor[N_MAX];
__device__ int   g_start[N_MAX + 1];
__device__ int   g_list[2 * E_MAX];                // 12.8 MB
__device__ int   g_is64;

// ---------------------------------------------------------------------------
// packed f32x2 helpers (Blackwell FFMA2 — only via PTX fma.rn.f32x2)
// ---------------------------------------------------------------------------
__device__ __forceinline__ u64 pack2(float lo, float hi) {
    u64 r; asm("mov.b64 %0, {%1, %2};" : "=l"(r) : "f"(lo), "f"(hi)); return r;
}
__device__ __forceinline__ float2 unpack2(u64 v) {
    float2 f; asm("mov.b64 {%0, %1}, %2;" : "=f"(f.x), "=f"(f.y) : "l"(v)); return f;
}
__device__ __forceinline__ u64 fma2(u64 a, u64 b, u64 c) {
    u64 d; asm("fma.rn.f32x2 %0, %1, %2, %3;" : "=l"(d) : "l"(a), "l"(b), "l"(c)); return d;
}

// node id for concatenated entry i in [0, 2E):  idx = concat(future, past)
// edge_index layout [2,E]: row0 = past, row1 = future
__device__ __forceinline__ int load_node(const void* ei, int i, int E, int is64) {
    long long pos = (i < E) ? (long long)E + i : (long long)i - E;
    if (is64) return (int)__ldg(&((const long long*)ei)[pos]);
    return __ldg(&((const int*)ei)[pos]);
}

// ---------------------------------------------------------------------------
// Kernel 1: zero deg/cursor + detect edge_index dtype
// ---------------------------------------------------------------------------
__global__ void init_kernel(int N, const int* __restrict__ edge_index_raw) {
    int i = blockIdx.x * blockDim.x + threadIdx.x;
    if (i < N) { g_deg[i] = 0; g_cursor[i] = 0; }
    if (blockIdx.x == 0 && threadIdx.x == 0) {
        int all_zero = 1;
#pragma unroll
        for (int k = 0; k < 8; k++)
            if (edge_index_raw[2 * k + 1] != 0) all_zero = 0;
        g_is64 = all_zero;
    }
}

// ---------------------------------------------------------------------------
// Kernel 2: per-node degree count over the 2E concatenated entries
// ---------------------------------------------------------------------------
__global__ void count_kernel(const void* __restrict__ edge_index, int E, int N) {
    int i = blockIdx.x * blockDim.x + threadIdx.x;
    if (i >= 2 * E) return;
    int is64 = g_is64;
    int node = load_node(edge_index, i, E, is64);
    if ((unsigned)node < (unsigned)N) atomicAdd(&g_deg[node], 1);
}

// ---------------------------------------------------------------------------
// Kernel 3: exclusive prefix scan of deg -> start (single 1024-thread block)
// ---------------------------------------------------------------------------
__global__ void __launch_bounds__(1024) scan_kernel(int N) {
    __shared__ int sums[1024];
    int tid = threadIdx.x;
    int chunk = (N + 1023) / 1024;
    int lo = tid * chunk;
    int hi = min(lo + chunk, N);

    int s = 0;
    for (int i = lo; i < hi; i++) s += g_deg[i];
    sums[tid] = s;
    __syncthreads();

    // inclusive Hillis-Steele scan
    for (int off = 1; off < 1024; off <<= 1) {
        int v = (tid >= off) ? sums[tid - off] : 0;
        __syncthreads();
        sums[tid] += v;
        __syncthreads();
    }

    int run = (tid == 0) ? 0 : sums[tid - 1];
    for (int i = lo; i < hi; i++) { g_start[i] = run; run += g_deg[i]; }
    if (tid == 1023) g_start[N] = sums[1023];
}

// ---------------------------------------------------------------------------
// Kernel 4: fill CSR edge lists (atomic cursor per node)
// ---------------------------------------------------------------------------
__global__ void fill_kernel(const void* __restrict__ edge_index, int E, int N) {
    int i = blockIdx.x * blockDim.x + threadIdx.x;
    if (i >= 2 * E) return;
    int is64 = g_is64;
    int node = load_node(edge_index, i, E, is64);
    if ((unsigned)node >= (unsigned)N) return;
    int e = (i < E) ? i : i - E;   // source edge row
    int pos = g_start[node] + atomicAdd(&g_cursor[node], 1);
    g_list[pos] = e;
}

// ---------------------------------------------------------------------------
// Kernel 5: gather — one warp per node, no atomics.
// Each lane accumulates 2 floats (float2); edge row read = 256B coalesced.
// ---------------------------------------------------------------------------
__global__ void __launch_bounds__(256) gather_kernel(
    const float* __restrict__ edge_attr, int N) {

    int warp_id = (blockIdx.x * blockDim.x + threadIdx.x) >> 5;
    int lane = threadIdx.x & 31;
    if (warp_id >= N) return;

    int s = g_start[warp_id];
    int t = g_start[warp_id + 1];

    float2 acc0 = make_float2(0.f, 0.f);
    float2 acc1 = make_float2(0.f, 0.f);

    for (int base = s; base < t; base += 32) {
        int nb = min(32, t - base);
        int e = (base + lane < t) ? __ldg(&g_list[base + lane]) : 0;
#pragma unroll 4
        for (int j = 0; j < nb; j += 2) {
            int e0 = __shfl_sync(0xffffffff, e, j);
            float2 v0 = __ldg((const float2*)(edge_attr + (size_t)e0 * D_FEAT) + lane);
            if (j + 1 < nb) {
                int e1 = __shfl_sync(0xffffffff, e, j + 1);
                float2 v1 = __ldg((const float2*)(edge_attr + (size_t)e1 * D_FEAT) + lane);
                acc1.x += v1.x; acc1.y += v1.y;
            }
            acc0.x += v0.x; acc0.y += v0.y;
        }
    }

    float2 r = make_float2(acc0.x + acc1.x, acc0.y + acc1.y);
    ((float2*)(g_flow + (size_t)warp_id * D_FEAT))[lane] = r;
}

// ---------------------------------------------------------------------------
// Kernel 6: fused MLP with packed f32x2 FMA.
// out = relu(flow @ W1 + b1) @ W2 + b2.  W1/W2 in 64 KB shared.
// Hidden dim processed in 4 tiles of 32 to bound registers.
// ---------------------------------------------------------------------------
__global__ void __launch_bounds__(256) mlp_kernel(
    const float* __restrict__ W1, const float* __restrict__ b1,
    const float* __restrict__ W2, const float* __restrict__ b2,
    float* __restrict__ out, int N) {

    extern __shared__ float smem[];
    float* sW1 = smem;                    // [k][j] 64x128
    float* sW2 = smem + D_FEAT * H_FEAT;  // [j][m] 128x64

    for (int i = threadIdx.x; i < (D_FEAT * H_FEAT) / 4; i += blockDim.x) {
        ((float4*)sW1)[i] = ((const float4*)W1)[i];
        ((float4*)sW2)[i] = ((const float4*)W2)[i];
    }
    __syncthreads();

    int row = blockIdx.x * blockDim.x + threadIdx.x;
    if (row >= N) return;

    float x[D_FEAT];
    const float4* xr = (const float4*)(g_flow + (size_t)row * D_FEAT);
#pragma unroll
    for (int i = 0; i < D_FEAT / 4; i++) {
        float4 v = xr[i];
        x[4 * i + 0] = v.x; x[4 * i + 1] = v.y;
        x[4 * i + 2] = v.z; x[4 * i + 3] = v.w;
    }

    // 32 packed output accumulators, init with b2
    u64 accO[D_FEAT / 2];
#pragma unroll
    for (int m = 0; m < D_FEAT / 2; m++) {
        float2 bv = __ldg(((const float2*)b2) + m);
        accO[m] = pack2(bv.x, bv.y);
    }

#pragma unroll
    for (int jt = 0; jt < 4; jt++) {           // hidden tiles of 32
        u64 h[16];
#pragma unroll
        for (int p = 0; p < 16; p++) {
            float2 bv = __ldg(((const float2*)b1) + jt * 16 + p);
            h[p] = pack2(bv.x, bv.y);
        }

        // stage 1: h += x_k * W1[k, tile]
        for (int k = 0; k < D_FEAT; k++) {
            u64 xk = pack2(x[k], x[k]);
            const ulonglong2* w = (const ulonglong2*)(sW1 + k * H_FEAT + jt * 32);
#pragma unroll
            for (int q = 0; q < 8; q++) {
                ulonglong2 wv = w[q];
                h[2 * q + 0] = fma2(xk, wv.x, h[2 * q + 0]);
                h[2 * q + 1] = fma2(xk, wv.y, h[2 * q + 1]);
            }
        }

        // relu + stage 2: accO += h_j * W2[j, :]
#pragma unroll
        for (int p = 0; p < 16; p++) {
            float2 hv = unpack2(h[p]);
            hv.x = fmaxf(hv.x, 0.f);
            hv.y = fmaxf(hv.y, 0.f);
            u64 h0 = pack2(hv.x, hv.x);
            u64 h1 = pack2(hv.y, hv.y);
            int j0 = jt * 32 + 2 * p;
            const ulonglong2* wa = (const ulonglong2*)(sW2 + (size_t)j0 * D_FEAT);
            const ulonglong2* wb = (const ulonglong2*)(sW2 + (size_t)(j0 + 1) * D_FEAT);
#pragma unroll
            for (int q = 0; q < 16; q++) {
                ulonglong2 va = wa[q];
                ulonglong2 vb = wb[q];
                accO[2 * q + 0] = fma2(h0, va.x, accO[2 * q + 0]);
                accO[2 * q + 0] = fma2(h1, vb.x, accO[2 * q + 0]);
                accO[2 * q + 1] = fma2(h0, va.y, accO[2 * q + 1]);
                accO[2 * q + 1] = fma2(h1, vb.y, accO[2 * q + 1]);
            }
        }
    }

    ulonglong2* orow = (ulonglong2*)(out + (size_t)row * D_FEAT);
#pragma unroll
    for (int q = 0; q < 16; q++) {
        ulonglong2 v; v.x = accO[2 * q]; v.y = accO[2 * q + 1];
        orow[q] = v;
    }
}

// ---------------------------------------------------------------------------
// kernel_launch
// ---------------------------------------------------------------------------
extern "C" void kernel_launch(void* const* d_in, const int* in_sizes, int n_in,
                              void* d_out, int out_size) {
    int idx = 0;
    const void* edge_index = d_in[idx];
    idx++;
    const float* edge_attr = (const float*)d_in[idx];
    int E = in_sizes[idx] / D_FEAT;   // edge_attr [E,64]
    idx++;
    while (idx < n_in && in_sizes[idx] <= 1) idx++;  // skip scalar num_nodes
    const float* W1 = (const float*)d_in[idx++];
    const float* b1 = (const float*)d_in[idx++];
    const float* W2 = (const float*)d_in[idx++];
    const float* b2 = (const float*)d_in[idx++];
    float* out = (float*)d_out;

    int N = out_size / D_FEAT;  // 100000

    // 1) zero deg/cursor + dtype detect
    init_kernel<<<(N + 255) / 256, 256>>>(N, (const int*)edge_index);

    // 2) degree count over 2E entries
    {
        int blocks = (2 * E + 255) / 256;
        count_kernel<<<blocks, 256>>>(edge_index, E, N);
    }

    // 3) exclusive scan -> start
    scan_kernel<<<1, 1024>>>(N);

    // 4) CSR fill
    {
        int blocks = (2 * E + 255) / 256;
        fill_kernel<<<blocks, 256>>>(edge_index, E, N);
    }

    // 5) gather (warp per node)
    {
        long long threads = (long long)N * 32;
        int blocks = (int)((threads + 255) / 256);
        gather_kernel<<<blocks, 256>>>(edge_attr, N);
    }

    // 6) MLP (f32x2 packed)
    {
        int blocks = (N + 255) / 256;
        size_t shmem = 2 * (size_t)D_FEAT * H_FEAT * sizeof(float);  // 64 KB
        cudaFuncSetAttribute(mlp_kernel,
                             cudaFuncAttributeMaxDynamicSharedMemorySize,
                             (int)shmem);
        mlp_kernel<<<blocks, 256, shmem>>>(W1, b1, W2, b2, out, N);
    }
}

// round 4
// speedup vs baseline: 1.5523x; 1.5523x over previous
#include <cuda_runtime.h>
#include <cuda_bf16.h>
#include <cstdint>

#define D_FEAT 64
#define H_FEAT 128
#define N_MAX 100000

typedef unsigned long long u64;

__device__ float g_flow[(size_t)N_MAX * D_FEAT];  // 25.6 MB accumulator
__device__ int   g_is64;

// ---------------------------------------------------------------------------
// packed f32x2 helpers (Blackwell FFMA2 — only via PTX fma.rn.f32x2)
// ---------------------------------------------------------------------------
__device__ __forceinline__ u64 pack2(float lo, float hi) {
    u64 r; asm("mov.b64 %0, {%1, %2};" : "=l"(r) : "f"(lo), "f"(hi)); return r;
}
__device__ __forceinline__ float2 unpack2(u64 v) {
    float2 f; asm("mov.b64 {%0, %1}, %2;" : "=f"(f.x), "=f"(f.y) : "l"(v)); return f;
}
__device__ __forceinline__ u64 fma2(u64 a, u64 b, u64 c) {
    u64 d; asm("fma.rn.f32x2 %0, %1, %2, %3;" : "=l"(d) : "l"(a), "l"(b), "l"(c)); return d;
}

// ---------------------------------------------------------------------------
// Kernel 1: zero accumulator + detect edge_index dtype
// ---------------------------------------------------------------------------
__global__ void zero_kernel(int n_float4, const int* __restrict__ edge_index_raw) {
    int i = blockIdx.x * blockDim.x + threadIdx.x;
    if (i < n_float4) {
        ((float4*)g_flow)[i] = make_float4(0.f, 0.f, 0.f, 0.f);
    }
    if (blockIdx.x == 0 && threadIdx.x == 0) {
        // int64 node ids are < 2^31 nonneg -> every odd 32-bit word is 0.
        int all_zero = 1;
#pragma unroll
        for (int k = 0; k < 8; k++)
            if (edge_index_raw[2 * k + 1] != 0) all_zero = 0;
        g_is64 = all_zero;
    }
}

// ---------------------------------------------------------------------------
// Kernel 2: scatter-add edge_attr into both endpoints (L2-resident RED.v4).
// One thread per (edge, 16B chunk); edge row read once, RED'd twice.
// ---------------------------------------------------------------------------
__device__ __forceinline__ void red_add_v4(float* addr, float4 v) {
    size_t gaddr = __cvta_generic_to_global(addr);
    asm volatile("red.global.add.v4.f32 [%0], {%1, %2, %3, %4};"
                 :: "l"(gaddr), "f"(v.x), "f"(v.y), "f"(v.z), "f"(v.w)
                 : "memory");
}

__global__ void scatter_kernel(const void* __restrict__ edge_index,
                               const float* __restrict__ edge_attr,
                               int E, int N) {
    long long t = (long long)blockIdx.x * blockDim.x + threadIdx.x;
    int e = (int)(t >> 4);
    int c = (int)(t & 15);
    if (e >= E) return;

    long long past, future;
    if (g_is64) {
        const long long* ei = (const long long*)edge_index;
        past   = __ldg(&ei[e]);
        future = __ldg(&ei[(size_t)E + e]);
    } else {
        const int* ei = (const int*)edge_index;
        past   = __ldg(&ei[e]);
        future = __ldg(&ei[(size_t)E + e]);
    }

    float4 v = ((const float4*)edge_attr)[(size_t)e * 16 + c];

    if ((unsigned long long)future < (unsigned long long)N)
        red_add_v4(g_flow + (size_t)future * D_FEAT + c * 4, v);
    if ((unsigned long long)past < (unsigned long long)N)
        red_add_v4(g_flow + (size_t)past * D_FEAT + c * 4, v);
}

// ---------------------------------------------------------------------------
// Kernel 3: fused MLP with packed f32x2 FMA (FFMA2).
// out = relu(flow @ W1 + b1) @ W2 + b2.  W1/W2 in 64 KB shared (broadcast).
// One node row per thread; hidden dim in 4 tiles of 32.
// ---------------------------------------------------------------------------
__global__ void __launch_bounds__(256) mlp_kernel(
    const float* __restrict__ W1, const float* __restrict__ b1,
    const float* __restrict__ W2, const float* __restrict__ b2,
    float* __restrict__ out, int N) {

    extern __shared__ float smem[];
    float* sW1 = smem;                    // [k][j] 64x128
    float* sW2 = smem + D_FEAT * H_FEAT;  // [j][m] 128x64

    for (int i = threadIdx.x; i < (D_FEAT * H_FEAT) / 4; i += blockDim.x) {
        ((float4*)sW1)[i] = ((const float4*)W1)[i];
        ((float4*)sW2)[i] = ((const float4*)W2)[i];
    }
    __syncthreads();

    int row = blockIdx.x * blockDim.x + threadIdx.x;
    if (row >= N) return;

    float x[D_FEAT];
    const float4* xr = (const float4*)(g_flow + (size_t)row * D_FEAT);
#pragma unroll
    for (int i = 0; i < D_FEAT / 4; i++) {
        float4 v = xr[i];
        x[4 * i + 0] = v.x; x[4 * i + 1] = v.y;
        x[4 * i + 2] = v.z; x[4 * i + 3] = v.w;
    }

    // 32 packed output accumulators, init with b2
    u64 accO[D_FEAT / 2];
#pragma unroll
    for (int m = 0; m < D_FEAT / 2; m++) {
        float2 bv = __ldg(((const float2*)b2) + m);
        accO[m] = pack2(bv.x, bv.y);
    }

#pragma unroll
    for (int jt = 0; jt < 4; jt++) {           // hidden tiles of 32
        u64 h[16];
#pragma unroll
        for (int p = 0; p < 16; p++) {
            float2 bv = __ldg(((const float2*)b1) + jt * 16 + p);
            h[p] = pack2(bv.x, bv.y);
        }

        // stage 1: h += x_k * W1[k, tile]
        for (int k = 0; k < D_FEAT; k++) {
            u64 xk = pack2(x[k], x[k]);
            const ulonglong2* w = (const ulonglong2*)(sW1 + k * H_FEAT + jt * 32);
#pragma unroll
            for (int q = 0; q < 8; q++) {
                ulonglong2 wv = w[q];
                h[2 * q + 0] = fma2(xk, wv.x, h[2 * q + 0]);
                h[2 * q + 1] = fma2(xk, wv.y, h[2 * q + 1]);
            }
        }

        // relu + stage 2: accO += h_j * W2[j, :]
#pragma unroll
        for (int p = 0; p < 16; p++) {
            float2 hv = unpack2(h[p]);
            hv.x = fmaxf(hv.x, 0.f);
            hv.y = fmaxf(hv.y, 0.f);
            u64 h0 = pack2(hv.x, hv.x);
            u64 h1 = pack2(hv.y, hv.y);
            int j0 = jt * 32 + 2 * p;
            const ulonglong2* wa = (const ulonglong2*)(sW2 + (size_t)j0 * D_FEAT);
            const ulonglong2* wb = (const ulonglong2*)(sW2 + (size_t)(j0 + 1) * D_FEAT);
#pragma unroll
            for (int q = 0; q < 16; q++) {
                ulonglong2 va = wa[q];
                ulonglong2 vb = wb[q];
                accO[2 * q + 0] = fma2(h0, va.x, accO[2 * q + 0]);
                accO[2 * q + 0] = fma2(h1, vb.x, accO[2 * q + 0]);
                accO[2 * q + 1] = fma2(h0, va.y, accO[2 * q + 1]);
                accO[2 * q + 1] = fma2(h1, vb.y, accO[2 * q + 1]);
            }
        }
    }

    ulonglong2* orow = (ulonglong2*)(out + (size_t)row * D_FEAT);
#pragma unroll
    for (int q = 0; q < 16; q++) {
        ulonglong2 v; v.x = accO[2 * q]; v.y = accO[2 * q + 1];
        orow[q] = v;
    }
}

// ---------------------------------------------------------------------------
// kernel_launch
// ---------------------------------------------------------------------------
extern "C" void kernel_launch(void* const* d_in, const int* in_sizes, int n_in,
                              void* d_out, int out_size) {
    int idx = 0;
    const void* edge_index = d_in[idx];
    idx++;
    const float* edge_attr = (const float*)d_in[idx];
    int E = in_sizes[idx] / D_FEAT;   // edge_attr [E,64]
    idx++;
    while (idx < n_in && in_sizes[idx] <= 1) idx++;  // skip scalar num_nodes
    const float* W1 = (const float*)d_in[idx++];
    const float* b1 = (const float*)d_in[idx++];
    const float* W2 = (const float*)d_in[idx++];
    const float* b2 = (const float*)d_in[idx++];
    float* out = (float*)d_out;

    int N = out_size / D_FEAT;  // 100000

    // 1) zero accumulator + dtype detect
    {
        int n_f4 = (N * D_FEAT) / 4;
        zero_kernel<<<(n_f4 + 255) / 256, 256>>>(n_f4, (const int*)edge_index);
    }

    // 2) scatter-add
    {
        long long threads = (long long)E * 16;
        int blocks = (int)((threads + 255) / 256);
        scatter_kernel<<<blocks, 256>>>(edge_index, edge_attr, E, N);
    }

    // 3) MLP (f32x2 packed)
    {
        int blocks = (N + 255) / 256;
        size_t shmem = 2 * (size_t)D_FEAT * H_FEAT * sizeof(float);  // 64 KB
        cudaFuncSetAttribute(mlp_kernel,
                             cudaFuncAttributeMaxDynamicSharedMemorySize,
                             (int)shmem);
        mlp_kernel<<<blocks, 256, shmem>>>(W1, b1, W2, b2, out, N);
    }
}